// round 1
// baseline (speedup 1.0000x reference)
#include <cuda_runtime.h>
#include <cstdint>

// Problem constants
#define K_TOTAL 4096
#define N_TOTAL 11008
#define M_TOTAL 8192
#define NGROUPS 704512          // IN_F*OUT_F/64

// Scratch (static device globals: allowed; no allocation at runtime)
__device__ float g_W[(size_t)N_TOTAL * K_TOTAL];   // dequantized, tf32-rounded, [out][in] K-major
__device__ float g_x[(size_t)M_TOTAL * K_TOTAL];   // tf32-rounded activations

__device__ __forceinline__ uint32_t f2tf32(float f) {
    uint32_t u;
    asm("cvt.rna.tf32.f32 %0, %1;" : "=r"(u) : "f"(f));
    return u;
}

// ---------------------------------------------------------------------------
// Kernel 1: dequantize packed 4-bit weights.
// W_q: [32, NGROUPS] int32 (one byte per int). Row r<32 = high nibble,
// r in [32,64) = low nibble of row r-32. W_r flat index = r*NGROUPS + g,
// and reshape(OUT_F, IN_F) keeps that flat order, so g_W is indexed flat.
// ---------------------------------------------------------------------------
__global__ void dequant_w_kernel(const int* __restrict__ Wq,
                                 const float* __restrict__ scale,
                                 const float* __restrict__ zero) {
    int idx = blockIdx.x * blockDim.x + threadIdx.x;
    const int total = 32 * NGROUPS;
    if (idx >= total) return;
    int g = idx % NGROUPS;
    int q = Wq[idx];
    float z = zero[g];
    float s = scale[g];
    float hi = (float)((q >> 4) & 0xF);
    float lo = (float)(q & 0xF);
    g_W[idx]         = __uint_as_float(f2tf32((hi - z) * s));
    g_W[idx + total] = __uint_as_float(f2tf32((lo - z) * s));
}

// ---------------------------------------------------------------------------
// Kernel 2: round x to tf32 (RNA) so the MMA sees round-to-nearest operands,
// not the biased truncation the HMMA unit applies to raw fp32.
// ---------------------------------------------------------------------------
__global__ void roundx_kernel(const float4* __restrict__ x, int n4) {
    int i = blockIdx.x * blockDim.x + threadIdx.x;
    if (i >= n4) return;
    float4 v = x[i];
    float4 o;
    o.x = __uint_as_float(f2tf32(v.x));
    o.y = __uint_as_float(f2tf32(v.y));
    o.z = __uint_as_float(f2tf32(v.z));
    o.w = __uint_as_float(f2tf32(v.w));
    reinterpret_cast<float4*>(g_x)[i] = o;
}

// ---------------------------------------------------------------------------
// Kernel 3: tf32 tensor-core GEMM.
//   C[m][n] = sum_k g_x[m][k] * g_W[n][k] + bias[n]
// Block tile 128x128x32, 256 threads (8 warps as 2(M) x 4(N), warp tile 64x32),
// mma.sync.m16n8k8.tf32, 2-stage cp.async pipeline, XOR-swizzled smem.
// Smem element (row,col) -> float offset row*32 + (((col>>2)+row)&7)*4 + (col&3)
//   - cp.async writes 16B chunks: chunk cc -> physical chunk (cc+row)&7
//   - fragment reads (8 rows x 4 cols per issue) hit 32 distinct banks.
// ---------------------------------------------------------------------------
__global__ void __launch_bounds__(256, 2)
gemm_tf32_kernel(const float* __restrict__ bias, float* __restrict__ C) {
    extern __shared__ float smem[];   // As: [2][128][32] at 0, Bs at +8192 floats

    // CTA swizzle: stripes of 8 M-tiles so B panels + 8 A panels fit L2.
    const int tiles_n = N_TOTAL / 128;   // 86
    const int GRP = 8;
    int gid = blockIdx.x;
    int stripe = gid / (GRP * tiles_n);
    int rem = gid - stripe * (GRP * tiles_n);
    int tm = stripe * GRP + (rem % GRP);
    int tn = rem / GRP;
    const int m0 = tm * 128;
    const int n0 = tn * 128;

    const int tid  = threadIdx.x;
    const int lane = tid & 31;
    const int warp = tid >> 5;
    const int wm   = warp & 1;      // 2 warps along M
    const int wn   = warp >> 1;     // 4 warps along N
    const int gID  = lane >> 2;
    const int t4   = lane & 3;

    uint32_t smem_b = (uint32_t)__cvta_generic_to_shared(smem);

    const float* Ag = g_x + (size_t)m0 * K_TOTAL;
    const float* Bg = g_W + (size_t)n0 * K_TOTAL;

    float acc[4][4][4];
#pragma unroll
    for (int i = 0; i < 4; i++)
#pragma unroll
        for (int j = 0; j < 4; j++)
#pragma unroll
            for (int k = 0; k < 4; k++) acc[i][j][k] = 0.f;

    auto issue = [&](int kt, int stage) {
        int kbase = kt * 32;
#pragma unroll
        for (int t = 0; t < 4; t++) {
            int idx = t * 256 + tid;
            int row = idx >> 3;
            int cc  = idx & 7;
            int pc  = (cc + row) & 7;
            uint32_t da = smem_b + stage * 16384 + row * 128 + pc * 16;
            uint32_t db = da + 32768;
            const float* sa = Ag + (size_t)row * K_TOTAL + kbase + cc * 4;
            const float* sb = Bg + (size_t)row * K_TOTAL + kbase + cc * 4;
            asm volatile("cp.async.cg.shared.global [%0], [%1], 16;\n" :: "r"(da), "l"(sa));
            asm volatile("cp.async.cg.shared.global [%0], [%1], 16;\n" :: "r"(db), "l"(sb));
        }
        asm volatile("cp.async.commit_group;\n" ::: "memory");
    };

    auto Aat = [&](int stage, int row, int col) -> uint32_t {
        return __float_as_uint(
            smem[stage * 4096 + row * 32 + ((((col >> 2) + row) & 7) << 2) + (col & 3)]);
    };
    auto Bat = [&](int stage, int row, int col) -> uint32_t {
        return __float_as_uint(
            smem[8192 + stage * 4096 + row * 32 + ((((col >> 2) + row) & 7) << 2) + (col & 3)]);
    };

    auto compute = [&](int stage) {
#pragma unroll
        for (int s8 = 0; s8 < 4; s8++) {
            int k0 = s8 * 8;
            uint32_t a[4][4], b[4][2];
#pragma unroll
            for (int mt = 0; mt < 4; mt++) {
                int r = wm * 64 + mt * 16 + gID;
                a[mt][0] = Aat(stage, r,     k0 + t4);
                a[mt][1] = Aat(stage, r + 8, k0 + t4);
                a[mt][2] = Aat(stage, r,     k0 + t4 + 4);
                a[mt][3] = Aat(stage, r + 8, k0 + t4 + 4);
            }
#pragma unroll
            for (int nt = 0; nt < 4; nt++) {
                int r = wn * 32 + nt * 8 + gID;
                b[nt][0] = Bat(stage, r, k0 + t4);
                b[nt][1] = Bat(stage, r, k0 + t4 + 4);
            }
#pragma unroll
            for (int mt = 0; mt < 4; mt++)
#pragma unroll
                for (int nt = 0; nt < 4; nt++) {
                    asm volatile(
                        "mma.sync.aligned.m16n8k8.row.col.f32.tf32.tf32.f32 "
                        "{%0,%1,%2,%3}, {%4,%5,%6,%7}, {%8,%9}, {%0,%1,%2,%3};\n"
                        : "+f"(acc[mt][nt][0]), "+f"(acc[mt][nt][1]),
                          "+f"(acc[mt][nt][2]), "+f"(acc[mt][nt][3])
                        : "r"(a[mt][0]), "r"(a[mt][1]), "r"(a[mt][2]), "r"(a[mt][3]),
                          "r"(b[nt][0]), "r"(b[nt][1]));
                }
        }
    };

    const int NK = K_TOTAL / 32;   // 128
    issue(0, 0);
    asm volatile("cp.async.wait_group 0;\n" ::: "memory");
    __syncthreads();

    for (int kt = 0; kt < NK; kt++) {
        int st = kt & 1;
        if (kt + 1 < NK) issue(kt + 1, st ^ 1);
        compute(st);
        asm volatile("cp.async.wait_group 0;\n" ::: "memory");
        __syncthreads();
    }

    // Epilogue: add bias, write fp32 output.
    float2 bv[4];
#pragma unroll
    for (int nt = 0; nt < 4; nt++) {
        int col = n0 + wn * 32 + nt * 8 + t4 * 2;
        bv[nt] = *reinterpret_cast<const float2*>(bias + col);
    }
#pragma unroll
    for (int mt = 0; mt < 4; mt++) {
#pragma unroll
        for (int nt = 0; nt < 4; nt++) {
            int row0 = m0 + wm * 64 + mt * 16 + gID;
            int col  = n0 + wn * 32 + nt * 8 + t4 * 2;
            float2 v0 = make_float2(acc[mt][nt][0] + bv[nt].x, acc[mt][nt][1] + bv[nt].y);
            float2 v1 = make_float2(acc[mt][nt][2] + bv[nt].x, acc[mt][nt][3] + bv[nt].y);
            *reinterpret_cast<float2*>(C + (size_t)row0 * N_TOTAL + col)       = v0;
            *reinterpret_cast<float2*>(C + (size_t)(row0 + 8) * N_TOTAL + col) = v1;
        }
    }
}

// ---------------------------------------------------------------------------
// Launch. Inputs (metadata order): x, W_q, scale, zero, bias. Output fp32.
// All launches on the capture stream; no allocs, no syncs.
// ---------------------------------------------------------------------------
extern "C" void kernel_launch(void* const* d_in, const int* in_sizes, int n_in,
                              void* d_out, int out_size) {
    const float* x     = (const float*)d_in[0];
    const int*   Wq    = (const int*)d_in[1];
    const float* scale = (const float*)d_in[2];
    const float* zero  = (const float*)d_in[3];
    const float* bias  = (const float*)d_in[4];
    float* out = (float*)d_out;

    // 1) dequantize weights (both nibbles per thread)
    {
        int total = 32 * NGROUPS;
        int threads = 256;
        int blocks = (total + threads - 1) / threads;
        dequant_w_kernel<<<blocks, threads>>>(Wq, scale, zero);
    }
    // 2) tf32-round activations
    {
        int n4 = (M_TOTAL * K_TOTAL) / 4;
        int threads = 256;
        int blocks = (n4 + threads - 1) / threads;
        roundx_kernel<<<blocks, threads>>>((const float4*)x, n4);
    }
    // 3) GEMM
    {
        cudaFuncSetAttribute(gemm_tf32_kernel,
                             cudaFuncAttributeMaxDynamicSharedMemorySize, 65536);
        int blocks = (M_TOTAL / 128) * (N_TOTAL / 128);   // 64 * 86 = 5504
        gemm_tf32_kernel<<<blocks, 256, 65536>>>(bias, out);
    }
}

// round 3
// speedup vs baseline: 1.8571x; 1.8571x over previous
#include <cuda_runtime.h>
#include <cuda_fp16.h>
#include <cstdint>

// Problem constants
#define K_TOTAL 4096
#define N_TOTAL 11008
#define M_TOTAL 8192
#define NGROUPS 704512

// Scratch (static device globals)
__device__ __half g_W[(size_t)N_TOTAL * K_TOTAL];   // dequantized fp16, [out][in] K-major
__device__ __half g_x[(size_t)M_TOTAL * K_TOTAL];   // fp16 activations

// ---------------------------------------------------------------------------
// Kernel 1: dequantize packed 4-bit weights -> fp16. Two packed bytes/thread.
// ---------------------------------------------------------------------------
__global__ void dequant_w_kernel(const int2* __restrict__ Wq,
                                 const float2* __restrict__ scale,
                                 const float2* __restrict__ zero) {
    const int total = 32 * NGROUPS;
    int i = blockIdx.x * blockDim.x + threadIdx.x;   // pair index
    int base = i * 2;
    if (base >= total) return;
    int g2 = base % NGROUPS;              // even, never crosses a row boundary
    int2 q = Wq[i];
    float2 s = scale[g2 >> 1];
    float2 z = zero[g2 >> 1];
    float hi0 = (float)((q.x >> 4) & 0xF), lo0 = (float)(q.x & 0xF);
    float hi1 = (float)((q.y >> 4) & 0xF), lo1 = (float)(q.y & 0xF);
    __half2 h = __floats2half2_rn((hi0 - z.x) * s.x, (hi1 - z.y) * s.y);
    __half2 l = __floats2half2_rn((lo0 - z.x) * s.x, (lo1 - z.y) * s.y);
    *reinterpret_cast<__half2*>(g_W + base)         = h;
    *reinterpret_cast<__half2*>(g_W + base + total) = l;
}

// ---------------------------------------------------------------------------
// Kernel 2: convert x fp32 -> fp16 (RNE).
// ---------------------------------------------------------------------------
__global__ void convx_kernel(const float4* __restrict__ x, int n4) {
    int i = blockIdx.x * blockDim.x + threadIdx.x;
    if (i >= n4) return;
    float4 v = x[i];
    __half2 a = __floats2half2_rn(v.x, v.y);
    __half2 b = __floats2half2_rn(v.z, v.w);
    uint2 o;
    o.x = *reinterpret_cast<uint32_t*>(&a);
    o.y = *reinterpret_cast<uint32_t*>(&b);
    reinterpret_cast<uint2*>(g_x)[i] = o;
}

// ---------------------------------------------------------------------------
// Kernel 3: fp16 tensor-core GEMM (legacy mma.sync m16n8k16, fp32 accum).
// Block tile 128x128x64, 256 threads (8 warps: 2(M) x 4(N), warp tile 64x32),
// 4-stage cp.async pipeline, XOR-swizzled SMEM, ldmatrix fragment loads.
// SMEM row = 64 halfs = 128B = 8 chunks of 16B; chunk cc at row r lives at
// physical chunk cc ^ (r & 7). Conflict-free for cp.async stores and LDSM.
// ---------------------------------------------------------------------------
#define BK 64
#define STAGE_BYTES 32768            // A 16KB + B 16KB
#define NSTAGE 4
#define SMEM_TOTAL (NSTAGE * STAGE_BYTES)   // 131072

#define CP_ASYNC16(dst, src) \
    asm volatile("cp.async.cg.shared.global [%0], [%1], 16;" :: "r"(dst), "l"(src))
#define CP_COMMIT() asm volatile("cp.async.commit_group;" ::: "memory")
#define CP_WAIT(n)  asm volatile("cp.async.wait_group %0;" :: "n"(n) : "memory")

#define LDSM_X4(r0, r1, r2, r3, a)                                            \
    asm volatile("ldmatrix.sync.aligned.m8n8.x4.shared.b16 {%0,%1,%2,%3}, [%4];" \
                 : "=r"(r0), "=r"(r1), "=r"(r2), "=r"(r3) : "r"(a))

__global__ void __launch_bounds__(256, 1)
gemm_fp16_kernel(const float* __restrict__ bias, float* __restrict__ C) {
    extern __shared__ char smem[];
    uint32_t sbase;
    asm("{ .reg .u64 t; cvta.to.shared.u64 t, %1; cvt.u32.u64 %0, t; }"
        : "=r"(sbase) : "l"(smem));

    const int tid  = threadIdx.x;
    const int lane = tid & 31;
    const int warp = tid >> 5;
    const int wm   = warp & 1;      // 2 warps along M (64 rows each)
    const int wn   = warp >> 1;     // 4 warps along N (32 cols each)
    const int gID  = lane >> 2;
    const int t4   = lane & 3;

    // CTA swizzle: stripes of 8 M-tiles keep B panels L2-resident.
    const int tiles_n = N_TOTAL / 128;   // 86
    const int GRP = 8;
    int gid = blockIdx.x;
    int stripe = gid / (GRP * tiles_n);
    int rem = gid - stripe * (GRP * tiles_n);
    int tm = stripe * GRP + (rem % GRP);
    int tn = rem / GRP;
    const int m0 = tm * 128;
    const int n0 = tn * 128;

    const __half* Ag = g_x + (size_t)m0 * K_TOTAL;
    const __half* Bg = g_W + (size_t)n0 * K_TOTAL;

    float acc[4][4][4];
#pragma unroll
    for (int i = 0; i < 4; i++)
#pragma unroll
        for (int j = 0; j < 4; j++)
#pragma unroll
            for (int k = 0; k < 4; k++) acc[i][j][k] = 0.f;

    // Per-thread cp.async addressing (4 A rows + 4 B rows per stage)
    auto issue = [&](int kt, int stage) {
        int kbase = kt * BK;
        uint32_t stg = sbase + stage * STAGE_BYTES;
#pragma unroll
        for (int t = 0; t < 4; t++) {            // A: 128 rows x 8 chunks
            int idx = t * 256 + tid;
            int row = idx >> 3, cc = idx & 7;
            uint32_t dst = stg + row * 128 + ((cc ^ (row & 7)) << 4);
            const __half* src = Ag + (size_t)row * K_TOTAL + kbase + cc * 8;
            CP_ASYNC16(dst, src);
        }
#pragma unroll
        for (int t = 0; t < 4; t++) {            // B: 128 rows x 8 chunks
            int idx = t * 256 + tid;
            int row = idx >> 3, cc = idx & 7;
            uint32_t dst = stg + 16384 + row * 128 + ((cc ^ (row & 7)) << 4);
            const __half* src = Bg + (size_t)row * K_TOTAL + kbase + cc * 8;
            CP_ASYNC16(dst, src);
        }
        CP_COMMIT();
    };

    // ldmatrix per-thread row/chunk decomposition
    const int arow = (lane & 7) + ((lane >> 3) & 1) * 8;   // 0..15
    const int akp  = lane >> 4;                            // 0/1 (k half)
    const int brow = (lane & 7) + (lane >> 4) * 8;         // 0..15
    const int bkp  = (lane >> 3) & 1;                      // 0/1 (k half)
    const int l7   = lane & 7;

    const uint32_t a_row_off = (uint32_t)(wm * 64 + arow) * 128;
    const uint32_t b_row_off = 16384u + (uint32_t)(wn * 32 + brow) * 128;

    auto compute = [&](int stage) {
        uint32_t stg = sbase + stage * STAGE_BYTES;
#pragma unroll
        for (int ks = 0; ks < 4; ks++) {
            uint32_t a[4][4], b[2][4];
#pragma unroll
            for (int mt = 0; mt < 4; mt++) {
                uint32_t addr = stg + a_row_off + (uint32_t)(mt * 16) * 128 +
                                (uint32_t)(((2 * ks + akp) ^ l7) << 4);
                LDSM_X4(a[mt][0], a[mt][1], a[mt][2], a[mt][3], addr);
            }
#pragma unroll
            for (int p = 0; p < 2; p++) {        // each covers 2 n-tiles of 8
                uint32_t addr = stg + b_row_off + (uint32_t)(p * 16) * 128 +
                                (uint32_t)(((2 * ks + bkp) ^ l7) << 4);
                LDSM_X4(b[p][0], b[p][1], b[p][2], b[p][3], addr);
            }
#pragma unroll
            for (int mt = 0; mt < 4; mt++)
#pragma unroll
                for (int nt = 0; nt < 4; nt++) {
                    uint32_t b0 = b[nt >> 1][(nt & 1) * 2];
                    uint32_t b1 = b[nt >> 1][(nt & 1) * 2 + 1];
                    asm volatile(
                        "mma.sync.aligned.m16n8k16.row.col.f32.f16.f16.f32 "
                        "{%0,%1,%2,%3}, {%4,%5,%6,%7}, {%8,%9}, {%0,%1,%2,%3};\n"
                        : "+f"(acc[mt][nt][0]), "+f"(acc[mt][nt][1]),
                          "+f"(acc[mt][nt][2]), "+f"(acc[mt][nt][3])
                        : "r"(a[mt][0]), "r"(a[mt][1]), "r"(a[mt][2]), "r"(a[mt][3]),
                          "r"(b0), "r"(b1));
                }
        }
    };

    const int NK = K_TOTAL / BK;   // 64

    issue(0, 0);
    issue(1, 1);
    issue(2, 2);

    for (int kt = 0; kt < NK; kt++) {
        if (kt < NK - 2)       CP_WAIT(2);
        else if (kt == NK - 2) CP_WAIT(1);
        else                   CP_WAIT(0);
        __syncthreads();
        if (kt + 3 < NK) issue(kt + 3, (kt + 3) & (NSTAGE - 1));
        compute(kt & (NSTAGE - 1));
    }

    // Epilogue: bias add + fp32 stores
    float2 bv[4];
#pragma unroll
    for (int nt = 0; nt < 4; nt++) {
        int col = n0 + wn * 32 + nt * 8 + t4 * 2;
        bv[nt] = *reinterpret_cast<const float2*>(bias + col);
    }
#pragma unroll
    for (int mt = 0; mt < 4; mt++) {
#pragma unroll
        for (int nt = 0; nt < 4; nt++) {
            int row0 = m0 + wm * 64 + mt * 16 + gID;
            int col  = n0 + wn * 32 + nt * 8 + t4 * 2;
            float2 v0 = make_float2(acc[mt][nt][0] + bv[nt].x, acc[mt][nt][1] + bv[nt].y);
            float2 v1 = make_float2(acc[mt][nt][2] + bv[nt].x, acc[mt][nt][3] + bv[nt].y);
            *reinterpret_cast<float2*>(C + (size_t)row0 * N_TOTAL + col)       = v0;
            *reinterpret_cast<float2*>(C + (size_t)(row0 + 8) * N_TOTAL + col) = v1;
        }
    }
}

// ---------------------------------------------------------------------------
// Launch. Inputs: x, W_q, scale, zero, bias. Output fp32.
// ---------------------------------------------------------------------------
extern "C" void kernel_launch(void* const* d_in, const int* in_sizes, int n_in,
                              void* d_out, int out_size) {
    const float* x     = (const float*)d_in[0];
    const int*   Wq    = (const int*)d_in[1];
    const float* scale = (const float*)d_in[2];
    const float* zero  = (const float*)d_in[3];
    const float* bias  = (const float*)d_in[4];
    float* out = (float*)d_out;

    {
        int pairs = (32 * NGROUPS) / 2;
        int threads = 256;
        int blocks = (pairs + threads - 1) / threads;
        dequant_w_kernel<<<blocks, threads>>>((const int2*)Wq,
                                              (const float2*)scale,
                                              (const float2*)zero);
    }
    {
        int n4 = (M_TOTAL * K_TOTAL) / 4;
        int threads = 256;
        int blocks = (n4 + threads - 1) / threads;
        convx_kernel<<<blocks, threads>>>((const float4*)x, n4);
    }
    {
        cudaFuncSetAttribute(gemm_fp16_kernel,
                             cudaFuncAttributeMaxDynamicSharedMemorySize, SMEM_TOTAL);
        int blocks = (M_TOTAL / 128) * (N_TOTAL / 128);   // 5504
        gemm_fp16_kernel<<<blocks, 256, SMEM_TOTAL>>>(bias, out);
    }
}

// round 4
// speedup vs baseline: 2.0776x; 1.1187x over previous
#include <cuda_runtime.h>
#include <cuda_fp16.h>
#include <cstdint>

// Problem constants
#define K_TOTAL 4096
#define N_TOTAL 11008
#define M_TOTAL 8192
#define NGROUPS 704512

// Scratch (static device globals)
__device__ __half g_W[(size_t)N_TOTAL * K_TOTAL];   // dequantized fp16, [out][in] K-major
__device__ __half g_x[(size_t)M_TOTAL * K_TOTAL];   // fp16 activations

// ---------------------------------------------------------------------------
// Kernel 1: dequantize packed 4-bit weights -> fp16. Two packed bytes/thread.
// ---------------------------------------------------------------------------
__global__ void dequant_w_kernel(const int2* __restrict__ Wq,
                                 const float2* __restrict__ scale,
                                 const float2* __restrict__ zero) {
    const int total = 32 * NGROUPS;
    int i = blockIdx.x * blockDim.x + threadIdx.x;   // pair index
    int base = i * 2;
    if (base >= total) return;
    int g2 = base % NGROUPS;              // even, never crosses a row boundary
    int2 q = Wq[i];
    float2 s = scale[g2 >> 1];
    float2 z = zero[g2 >> 1];
    float hi0 = (float)((q.x >> 4) & 0xF), lo0 = (float)(q.x & 0xF);
    float hi1 = (float)((q.y >> 4) & 0xF), lo1 = (float)(q.y & 0xF);
    __half2 h = __floats2half2_rn((hi0 - z.x) * s.x, (hi1 - z.y) * s.y);
    __half2 l = __floats2half2_rn((lo0 - z.x) * s.x, (lo1 - z.y) * s.y);
    *reinterpret_cast<__half2*>(g_W + base)         = h;
    *reinterpret_cast<__half2*>(g_W + base + total) = l;
}

// ---------------------------------------------------------------------------
// Kernel 2: convert x fp32 -> fp16 (RNE).
// ---------------------------------------------------------------------------
__global__ void convx_kernel(const float4* __restrict__ x, int n4) {
    int i = blockIdx.x * blockDim.x + threadIdx.x;
    if (i >= n4) return;
    float4 v = x[i];
    __half2 a = __floats2half2_rn(v.x, v.y);
    __half2 b = __floats2half2_rn(v.z, v.w);
    uint2 o;
    o.x = *reinterpret_cast<uint32_t*>(&a);
    o.y = *reinterpret_cast<uint32_t*>(&b);
    reinterpret_cast<uint2*>(g_x)[i] = o;
}

// ---------------------------------------------------------------------------
// Kernel 3: fp16 tensor-core GEMM (legacy mma.sync m16n8k16, fp32 accum).
// Block tile 256(M)x128(N)x64(K), 256 threads (8 warps: 4(M) x 2(N),
// warp tile 64x64). 4-stage cp.async pipeline, XOR-swizzled SMEM, ldmatrix.
// SMEM row = 64 halfs = 128B = 8 chunks of 16B; chunk cc at row r lives at
// physical chunk cc ^ (r & 7).
// ---------------------------------------------------------------------------
#define BK 64
#define TILE_M 256
#define TILE_N 128
#define A_BYTES (TILE_M * 128)                 // 32768
#define B_BYTES (TILE_N * 128)                 // 16384
#define STAGE_BYTES (A_BYTES + B_BYTES)        // 49152
#define NSTAGE 4
#define SMEM_TOTAL (NSTAGE * STAGE_BYTES)      // 196608

#define CP_ASYNC16(dst, src) \
    asm volatile("cp.async.cg.shared.global [%0], [%1], 16;" :: "r"(dst), "l"(src))
#define CP_COMMIT() asm volatile("cp.async.commit_group;" ::: "memory")
#define CP_WAIT(n)  asm volatile("cp.async.wait_group %0;" :: "n"(n) : "memory")

#define LDSM_X4(r0, r1, r2, r3, a)                                            \
    asm volatile("ldmatrix.sync.aligned.m8n8.x4.shared.b16 {%0,%1,%2,%3}, [%4];" \
                 : "=r"(r0), "=r"(r1), "=r"(r2), "=r"(r3) : "r"(a))

__global__ void __launch_bounds__(256, 1)
gemm_fp16_kernel(const float* __restrict__ bias, float* __restrict__ C) {
    extern __shared__ char smem[];
    uint32_t sbase;
    asm("{ .reg .u64 t; cvta.to.shared.u64 t, %1; cvt.u32.u64 %0, t; }"
        : "=r"(sbase) : "l"(smem));

    const int tid  = threadIdx.x;
    const int lane = tid & 31;
    const int warp = tid >> 5;
    const int wm   = warp & 3;      // 4 warps along M (64 rows each)
    const int wn   = warp >> 2;     // 2 warps along N (64 cols each)
    const int gID  = lane >> 2;
    const int t4   = lane & 3;

    // CTA swizzle: stripes of 8 M-tiles keep panels L2-resident.
    const int tiles_n = N_TOTAL / TILE_N;   // 86
    const int tiles_m = M_TOTAL / TILE_M;   // 32
    const int GRP = 8;
    int gid = blockIdx.x;
    int stripe = gid / (GRP * tiles_n);
    int rem = gid - stripe * (GRP * tiles_n);
    int tm = stripe * GRP + (rem % GRP);
    int tn = rem / GRP;
    if (tm >= tiles_m) return;   // (exact here: 32 % 8 == 0, but keep safe)
    const int m0 = tm * TILE_M;
    const int n0 = tn * TILE_N;

    const __half* Ag = g_x + (size_t)m0 * K_TOTAL;
    const __half* Bg = g_W + (size_t)n0 * K_TOTAL;

    float acc[4][8][4];
#pragma unroll
    for (int i = 0; i < 4; i++)
#pragma unroll
        for (int j = 0; j < 8; j++)
#pragma unroll
            for (int k = 0; k < 4; k++) acc[i][j][k] = 0.f;

    // Per-stage cp.async: A = 256 rows x 8 chunks (2048 slots -> 8/thread),
    //                     B = 128 rows x 8 chunks (1024 slots -> 4/thread).
    auto issue = [&](int kt, int stage) {
        int kbase = kt * BK;
        uint32_t stg = sbase + stage * STAGE_BYTES;
#pragma unroll
        for (int t = 0; t < 8; t++) {
            int idx = t * 256 + tid;
            int row = idx >> 3, cc = idx & 7;
            uint32_t dst = stg + row * 128 + ((cc ^ (row & 7)) << 4);
            const __half* src = Ag + (size_t)row * K_TOTAL + kbase + cc * 8;
            CP_ASYNC16(dst, src);
        }
#pragma unroll
        for (int t = 0; t < 4; t++) {
            int idx = t * 256 + tid;
            int row = idx >> 3, cc = idx & 7;
            uint32_t dst = stg + A_BYTES + row * 128 + ((cc ^ (row & 7)) << 4);
            const __half* src = Bg + (size_t)row * K_TOTAL + kbase + cc * 8;
            CP_ASYNC16(dst, src);
        }
        CP_COMMIT();
    };

    // ldmatrix per-thread row/chunk decomposition
    const int arow = (lane & 7) + ((lane >> 3) & 1) * 8;   // 0..15
    const int akp  = lane >> 4;                            // 0/1 (k half)
    const int brow = (lane & 7) + (lane >> 4) * 8;         // 0..15
    const int bkp  = (lane >> 3) & 1;                      // 0/1 (k half)
    const int l7   = lane & 7;

    const uint32_t a_row_off = (uint32_t)(wm * 64 + arow) * 128;
    const uint32_t b_row_off = (uint32_t)A_BYTES + (uint32_t)(wn * 64 + brow) * 128;

    auto compute = [&](int stage) {
        uint32_t stg = sbase + stage * STAGE_BYTES;
#pragma unroll
        for (int ks = 0; ks < 4; ks++) {
            uint32_t a[4][4], b[4][4];
#pragma unroll
            for (int mt = 0; mt < 4; mt++) {
                uint32_t addr = stg + a_row_off + (uint32_t)(mt * 16) * 128 +
                                (uint32_t)(((2 * ks + akp) ^ l7) << 4);
                LDSM_X4(a[mt][0], a[mt][1], a[mt][2], a[mt][3], addr);
            }
#pragma unroll
            for (int p = 0; p < 4; p++) {        // each covers 2 n-tiles of 8
                uint32_t addr = stg + b_row_off + (uint32_t)(p * 16) * 128 +
                                (uint32_t)(((2 * ks + bkp) ^ l7) << 4);
                LDSM_X4(b[p][0], b[p][1], b[p][2], b[p][3], addr);
            }
#pragma unroll
            for (int mt = 0; mt < 4; mt++)
#pragma unroll
                for (int nt = 0; nt < 8; nt++) {
                    uint32_t b0 = b[nt >> 1][(nt & 1) * 2];
                    uint32_t b1 = b[nt >> 1][(nt & 1) * 2 + 1];
                    asm volatile(
                        "mma.sync.aligned.m16n8k16.row.col.f32.f16.f16.f32 "
                        "{%0,%1,%2,%3}, {%4,%5,%6,%7}, {%8,%9}, {%0,%1,%2,%3};\n"
                        : "+f"(acc[mt][nt][0]), "+f"(acc[mt][nt][1]),
                          "+f"(acc[mt][nt][2]), "+f"(acc[mt][nt][3])
                        : "r"(a[mt][0]), "r"(a[mt][1]), "r"(a[mt][2]), "r"(a[mt][3]),
                          "r"(b0), "r"(b1));
                }
        }
    };

    const int NK = K_TOTAL / BK;   // 64

    issue(0, 0);
    issue(1, 1);
    issue(2, 2);

    for (int kt = 0; kt < NK; kt++) {
        if (kt < NK - 2)       CP_WAIT(2);
        else if (kt == NK - 2) CP_WAIT(1);
        else                   CP_WAIT(0);
        __syncthreads();
        if (kt + 3 < NK) issue(kt + 3, (kt + 3) & (NSTAGE - 1));
        compute(kt & (NSTAGE - 1));
    }

    // Epilogue: bias add + fp32 stores
    float2 bv[8];
#pragma unroll
    for (int nt = 0; nt < 8; nt++) {
        int col = n0 + wn * 64 + nt * 8 + t4 * 2;
        bv[nt] = *reinterpret_cast<const float2*>(bias + col);
    }
#pragma unroll
    for (int mt = 0; mt < 4; mt++) {
#pragma unroll
        for (int nt = 0; nt < 8; nt++) {
            int row0 = m0 + wm * 64 + mt * 16 + gID;
            int col  = n0 + wn * 64 + nt * 8 + t4 * 2;
            float2 v0 = make_float2(acc[mt][nt][0] + bv[nt].x, acc[mt][nt][1] + bv[nt].y);
            float2 v1 = make_float2(acc[mt][nt][2] + bv[nt].x, acc[mt][nt][3] + bv[nt].y);
            *reinterpret_cast<float2*>(C + (size_t)row0 * N_TOTAL + col)       = v0;
            *reinterpret_cast<float2*>(C + (size_t)(row0 + 8) * N_TOTAL + col) = v1;
        }
    }
}

// ---------------------------------------------------------------------------
// Launch. Inputs: x, W_q, scale, zero, bias. Output fp32.
// ---------------------------------------------------------------------------
extern "C" void kernel_launch(void* const* d_in, const int* in_sizes, int n_in,
                              void* d_out, int out_size) {
    const float* x     = (const float*)d_in[0];
    const int*   Wq    = (const int*)d_in[1];
    const float* scale = (const float*)d_in[2];
    const float* zero  = (const float*)d_in[3];
    const float* bias  = (const float*)d_in[4];
    float* out = (float*)d_out;

    {
        int pairs = (32 * NGROUPS) / 2;
        int threads = 256;
        int blocks = (pairs + threads - 1) / threads;
        dequant_w_kernel<<<blocks, threads>>>((const int2*)Wq,
                                              (const float2*)scale,
                                              (const float2*)zero);
    }
    {
        int n4 = (M_TOTAL * K_TOTAL) / 4;
        int threads = 256;
        int blocks = (n4 + threads - 1) / threads;
        convx_kernel<<<blocks, threads>>>((const float4*)x, n4);
    }
    {
        cudaFuncSetAttribute(gemm_fp16_kernel,
                             cudaFuncAttributeMaxDynamicSharedMemorySize, SMEM_TOTAL);
        int blocks = (M_TOTAL / TILE_M) * (N_TOTAL / TILE_N);   // 32 * 86 = 2752
        gemm_fp16_kernel<<<blocks, 256, SMEM_TOTAL>>>(bias, out);
    }
}

// round 5
// speedup vs baseline: 2.2516x; 1.0837x over previous
#include <cuda_runtime.h>
#include <cuda_fp16.h>
#include <cstdint>

// Problem constants
#define K_TOTAL 4096
#define N_TOTAL 11008
#define M_TOTAL 8192
#define NGROUPS 704512

// Scratch (static device globals)
__device__ __half g_W[(size_t)N_TOTAL * K_TOTAL];   // dequantized fp16, [out][in] K-major
__device__ __half g_x[(size_t)M_TOTAL * K_TOTAL];   // fp16 activations

// ---------------------------------------------------------------------------
// Kernel 1: dequantize packed 4-bit weights -> fp16. Two packed bytes/thread.
// ---------------------------------------------------------------------------
__global__ void dequant_w_kernel(const int2* __restrict__ Wq,
                                 const float2* __restrict__ scale,
                                 const float2* __restrict__ zero) {
    const int total = 32 * NGROUPS;
    int i = blockIdx.x * blockDim.x + threadIdx.x;   // pair index
    int base = i * 2;
    if (base >= total) return;
    int g2 = base % NGROUPS;
    int2 q = Wq[i];
    float2 s = scale[g2 >> 1];
    float2 z = zero[g2 >> 1];
    float hi0 = (float)((q.x >> 4) & 0xF), lo0 = (float)(q.x & 0xF);
    float hi1 = (float)((q.y >> 4) & 0xF), lo1 = (float)(q.y & 0xF);
    __half2 h = __floats2half2_rn((hi0 - z.x) * s.x, (hi1 - z.y) * s.y);
    __half2 l = __floats2half2_rn((lo0 - z.x) * s.x, (lo1 - z.y) * s.y);
    *reinterpret_cast<__half2*>(g_W + base)         = h;
    *reinterpret_cast<__half2*>(g_W + base + total) = l;
}

// ---------------------------------------------------------------------------
// Kernel 2: convert x fp32 -> fp16 (RNE).
// ---------------------------------------------------------------------------
__global__ void convx_kernel(const float4* __restrict__ x, int n4) {
    int i = blockIdx.x * blockDim.x + threadIdx.x;
    if (i >= n4) return;
    float4 v = x[i];
    __half2 a = __floats2half2_rn(v.x, v.y);
    __half2 b = __floats2half2_rn(v.z, v.w);
    uint2 o;
    o.x = *reinterpret_cast<uint32_t*>(&a);
    o.y = *reinterpret_cast<uint32_t*>(&b);
    reinterpret_cast<uint2*>(g_x)[i] = o;
}

// ---------------------------------------------------------------------------
// Kernel 3: fp16 tensor-core GEMM (legacy mma.sync m16n8k16, fp32 accum).
// Block tile 128x128x64, 256 threads (8 warps: 2(M) x 4(N), warp tile 64x32),
// 3-stage cp.async pipeline (96KB), 2 CTAs/SM for latency hiding.
// SMEM row = 64 halfs = 128B = 8 chunks of 16B; chunk cc at row r lives at
// physical chunk cc ^ (r & 7).
// ---------------------------------------------------------------------------
#define BK 64
#define STAGE_BYTES 32768            // A 16KB + B 16KB
#define NSTAGE 3
#define SMEM_TOTAL (NSTAGE * STAGE_BYTES)   // 98304

#define CP_ASYNC16(dst, src) \
    asm volatile("cp.async.cg.shared.global [%0], [%1], 16;" :: "r"(dst), "l"(src))
#define CP_COMMIT() asm volatile("cp.async.commit_group;" ::: "memory")
#define CP_WAIT(n)  asm volatile("cp.async.wait_group %0;" :: "n"(n) : "memory")

#define LDSM_X4(r0, r1, r2, r3, a)                                            \
    asm volatile("ldmatrix.sync.aligned.m8n8.x4.shared.b16 {%0,%1,%2,%3}, [%4];" \
                 : "=r"(r0), "=r"(r1), "=r"(r2), "=r"(r3) : "r"(a))

__global__ void __launch_bounds__(256, 2)
gemm_fp16_kernel(const float* __restrict__ bias, float* __restrict__ C) {
    extern __shared__ char smem[];
    uint32_t sbase;
    asm("{ .reg .u64 t; cvta.to.shared.u64 t, %1; cvt.u32.u64 %0, t; }"
        : "=r"(sbase) : "l"(smem));

    const int tid  = threadIdx.x;
    const int lane = tid & 31;
    const int warp = tid >> 5;
    const int wm   = warp & 1;      // 2 warps along M (64 rows each)
    const int wn   = warp >> 1;     // 4 warps along N (32 cols each)
    const int gID  = lane >> 2;
    const int t4   = lane & 3;

    // CTA swizzle: stripes of 8 M-tiles keep B panels L2-resident.
    const int tiles_n = N_TOTAL / 128;   // 86
    const int GRP = 8;
    int gid = blockIdx.x;
    int stripe = gid / (GRP * tiles_n);
    int rem = gid - stripe * (GRP * tiles_n);
    int tm = stripe * GRP + (rem % GRP);
    int tn = rem / GRP;
    const int m0 = tm * 128;
    const int n0 = tn * 128;

    const __half* Ag = g_x + (size_t)m0 * K_TOTAL;
    const __half* Bg = g_W + (size_t)n0 * K_TOTAL;

    float acc[4][4][4];
#pragma unroll
    for (int i = 0; i < 4; i++)
#pragma unroll
        for (int j = 0; j < 4; j++)
#pragma unroll
            for (int k = 0; k < 4; k++) acc[i][j][k] = 0.f;

    auto issue = [&](int kt, int stage) {
        int kbase = kt * BK;
        uint32_t stg = sbase + stage * STAGE_BYTES;
#pragma unroll
        for (int t = 0; t < 4; t++) {            // A: 128 rows x 8 chunks
            int idx = t * 256 + tid;
            int row = idx >> 3, cc = idx & 7;
            uint32_t dst = stg + row * 128 + ((cc ^ (row & 7)) << 4);
            const __half* src = Ag + (size_t)row * K_TOTAL + kbase + cc * 8;
            CP_ASYNC16(dst, src);
        }
#pragma unroll
        for (int t = 0; t < 4; t++) {            // B: 128 rows x 8 chunks
            int idx = t * 256 + tid;
            int row = idx >> 3, cc = idx & 7;
            uint32_t dst = stg + 16384 + row * 128 + ((cc ^ (row & 7)) << 4);
            const __half* src = Bg + (size_t)row * K_TOTAL + kbase + cc * 8;
            CP_ASYNC16(dst, src);
        }
        CP_COMMIT();
    };

    // ldmatrix per-thread row/chunk decomposition
    const int arow = (lane & 7) + ((lane >> 3) & 1) * 8;   // 0..15
    const int akp  = lane >> 4;                            // 0/1 (k half)
    const int brow = (lane & 7) + (lane >> 4) * 8;         // 0..15
    const int bkp  = (lane >> 3) & 1;                      // 0/1 (k half)
    const int l7   = lane & 7;

    const uint32_t a_row_off = (uint32_t)(wm * 64 + arow) * 128;
    const uint32_t b_row_off = 16384u + (uint32_t)(wn * 32 + brow) * 128;

    auto compute = [&](int stage) {
        uint32_t stg = sbase + stage * STAGE_BYTES;
#pragma unroll
        for (int ks = 0; ks < 4; ks++) {
            uint32_t a[4][4], b[2][4];
#pragma unroll
            for (int mt = 0; mt < 4; mt++) {
                uint32_t addr = stg + a_row_off + (uint32_t)(mt * 16) * 128 +
                                (uint32_t)(((2 * ks + akp) ^ l7) << 4);
                LDSM_X4(a[mt][0], a[mt][1], a[mt][2], a[mt][3], addr);
            }
#pragma unroll
            for (int p = 0; p < 2; p++) {        // each covers 2 n-tiles of 8
                uint32_t addr = stg + b_row_off + (uint32_t)(p * 16) * 128 +
                                (uint32_t)(((2 * ks + bkp) ^ l7) << 4);
                LDSM_X4(b[p][0], b[p][1], b[p][2], b[p][3], addr);
            }
#pragma unroll
            for (int mt = 0; mt < 4; mt++)
#pragma unroll
                for (int nt = 0; nt < 4; nt++) {
                    uint32_t b0 = b[nt >> 1][(nt & 1) * 2];
                    uint32_t b1 = b[nt >> 1][(nt & 1) * 2 + 1];
                    asm volatile(
                        "mma.sync.aligned.m16n8k16.row.col.f32.f16.f16.f32 "
                        "{%0,%1,%2,%3}, {%4,%5,%6,%7}, {%8,%9}, {%0,%1,%2,%3};\n"
                        : "+f"(acc[mt][nt][0]), "+f"(acc[mt][nt][1]),
                          "+f"(acc[mt][nt][2]), "+f"(acc[mt][nt][3])
                        : "r"(a[mt][0]), "r"(a[mt][1]), "r"(a[mt][2]), "r"(a[mt][3]),
                          "r"(b0), "r"(b1));
                }
        }
    };

    const int NK = K_TOTAL / BK;   // 64

    issue(0, 0);
    issue(1, 1);

    int stage = 0;
    for (int kt = 0; kt < NK; kt++) {
        if (kt == NK - 1) { CP_WAIT(0); } else { CP_WAIT(1); }
        __syncthreads();
        if (kt + 2 < NK) {
            int s2 = stage + 2; if (s2 >= NSTAGE) s2 -= NSTAGE;
            issue(kt + 2, s2);
        }
        compute(stage);
        stage = (stage + 1 == NSTAGE) ? 0 : stage + 1;
    }

    // Epilogue: bias add + fp32 stores
    float2 bv[4];
#pragma unroll
    for (int nt = 0; nt < 4; nt++) {
        int col = n0 + wn * 32 + nt * 8 + t4 * 2;
        bv[nt] = *reinterpret_cast<const float2*>(bias + col);
    }
#pragma unroll
    for (int mt = 0; mt < 4; mt++) {
#pragma unroll
        for (int nt = 0; nt < 4; nt++) {
            int row0 = m0 + wm * 64 + mt * 16 + gID;
            int col  = n0 + wn * 32 + nt * 8 + t4 * 2;
            float2 v0 = make_float2(acc[mt][nt][0] + bv[nt].x, acc[mt][nt][1] + bv[nt].y);
            float2 v1 = make_float2(acc[mt][nt][2] + bv[nt].x, acc[mt][nt][3] + bv[nt].y);
            *reinterpret_cast<float2*>(C + (size_t)row0 * N_TOTAL + col)       = v0;
            *reinterpret_cast<float2*>(C + (size_t)(row0 + 8) * N_TOTAL + col) = v1;
        }
    }
}

// ---------------------------------------------------------------------------
// Launch. Inputs: x, W_q, scale, zero, bias. Output fp32.
// ---------------------------------------------------------------------------
extern "C" void kernel_launch(void* const* d_in, const int* in_sizes, int n_in,
                              void* d_out, int out_size) {
    const float* x     = (const float*)d_in[0];
    const int*   Wq    = (const int*)d_in[1];
    const float* scale = (const float*)d_in[2];
    const float* zero  = (const float*)d_in[3];
    const float* bias  = (const float*)d_in[4];
    float* out = (float*)d_out;

    {
        int pairs = (32 * NGROUPS) / 2;
        int threads = 256;
        int blocks = (pairs + threads - 1) / threads;
        dequant_w_kernel<<<blocks, threads>>>((const int2*)Wq,
                                              (const float2*)scale,
                                              (const float2*)zero);
    }
    {
        int n4 = (M_TOTAL * K_TOTAL) / 4;
        int threads = 256;
        int blocks = (n4 + threads - 1) / threads;
        convx_kernel<<<blocks, threads>>>((const float4*)x, n4);
    }
    {
        cudaFuncSetAttribute(gemm_fp16_kernel,
                             cudaFuncAttributeMaxDynamicSharedMemorySize, SMEM_TOTAL);
        int blocks = (M_TOTAL / 128) * (N_TOTAL / 128);   // 5504
        gemm_fp16_kernel<<<blocks, 256, SMEM_TOTAL>>>(bias, out);
    }
}

// round 6
// speedup vs baseline: 2.3508x; 1.0441x over previous
#include <cuda_runtime.h>
#include <cuda_fp16.h>
#include <cstdint>

// Problem constants
#define K_TOTAL 4096
#define N_TOTAL 11008
#define M_TOTAL 8192
#define NGROUPS 704512

// Scratch (static device globals)
__device__ __half g_W[(size_t)N_TOTAL * K_TOTAL];   // dequantized fp16, [out][in] K-major
__device__ __half g_x[(size_t)M_TOTAL * K_TOTAL];   // fp16 activations

// ---------------------------------------------------------------------------
// Kernel 1: dequantize packed 4-bit weights -> fp16. Four packed bytes/thread,
// 8B stores to each half.
// ---------------------------------------------------------------------------
__global__ void dequant_w_kernel(const int4* __restrict__ Wq,
                                 const float4* __restrict__ scale,
                                 const float4* __restrict__ zero) {
    const int total = 32 * NGROUPS;
    int i = blockIdx.x * blockDim.x + threadIdx.x;   // quad index
    int base = i * 4;
    if (base >= total) return;
    int g4 = base % NGROUPS;              // multiple of 4, never crosses a row
    int4 q = Wq[i];
    float4 s = scale[g4 >> 2];
    float4 z = zero[g4 >> 2];

    float h0 = ((float)((q.x >> 4) & 0xF) - z.x) * s.x;
    float l0 = ((float)(q.x & 0xF)        - z.x) * s.x;
    float h1 = ((float)((q.y >> 4) & 0xF) - z.y) * s.y;
    float l1 = ((float)(q.y & 0xF)        - z.y) * s.y;
    float h2 = ((float)((q.z >> 4) & 0xF) - z.z) * s.z;
    float l2 = ((float)(q.z & 0xF)        - z.z) * s.z;
    float h3 = ((float)((q.w >> 4) & 0xF) - z.w) * s.w;
    float l3 = ((float)(q.w & 0xF)        - z.w) * s.w;

    __half2 hA = __floats2half2_rn(h0, h1), hB = __floats2half2_rn(h2, h3);
    __half2 lA = __floats2half2_rn(l0, l1), lB = __floats2half2_rn(l2, l3);
    uint2 hs, ls;
    hs.x = *reinterpret_cast<uint32_t*>(&hA); hs.y = *reinterpret_cast<uint32_t*>(&hB);
    ls.x = *reinterpret_cast<uint32_t*>(&lA); ls.y = *reinterpret_cast<uint32_t*>(&lB);
    *reinterpret_cast<uint2*>(g_W + base)         = hs;
    *reinterpret_cast<uint2*>(g_W + base + total) = ls;
}

// ---------------------------------------------------------------------------
// Kernel 2: convert x fp32 -> fp16 (RNE). 8 elements/thread, 16B store.
// ---------------------------------------------------------------------------
__global__ void convx_kernel(const float4* __restrict__ x, int n8) {
    int i = blockIdx.x * blockDim.x + threadIdx.x;
    if (i >= n8) return;
    float4 v0 = x[2 * i];
    float4 v1 = x[2 * i + 1];
    __half2 a = __floats2half2_rn(v0.x, v0.y);
    __half2 b = __floats2half2_rn(v0.z, v0.w);
    __half2 c = __floats2half2_rn(v1.x, v1.y);
    __half2 d = __floats2half2_rn(v1.z, v1.w);
    uint4 o;
    o.x = *reinterpret_cast<uint32_t*>(&a);
    o.y = *reinterpret_cast<uint32_t*>(&b);
    o.z = *reinterpret_cast<uint32_t*>(&c);
    o.w = *reinterpret_cast<uint32_t*>(&d);
    reinterpret_cast<uint4*>(g_x)[i] = o;
}

// ---------------------------------------------------------------------------
// Kernel 3: fp16 tensor-core GEMM (mma.sync m16n8k16, fp32 accum).
// Block tile 128x128x64, 8 warps (2Mx4N, warp tile 64x32), 3-stage cp.async
// pipeline (96KB), 2 CTAs/SM. cp.async issue interleaved into the MMA stream.
// ---------------------------------------------------------------------------
#define BK 64
#define STAGE_BYTES 32768            // A 16KB + B 16KB
#define NSTAGE 3
#define SMEM_TOTAL (NSTAGE * STAGE_BYTES)   // 98304

#define CP_ASYNC16(dst, src) \
    asm volatile("cp.async.cg.shared.global [%0], [%1], 16;" :: "r"(dst), "l"(src))
#define CP_COMMIT() asm volatile("cp.async.commit_group;" ::: "memory")
#define CP_WAIT(n)  asm volatile("cp.async.wait_group %0;" :: "n"(n) : "memory")

#define LDSM_X4(r0, r1, r2, r3, a)                                            \
    asm volatile("ldmatrix.sync.aligned.m8n8.x4.shared.b16 {%0,%1,%2,%3}, [%4];" \
                 : "=r"(r0), "=r"(r1), "=r"(r2), "=r"(r3) : "r"(a))

__global__ void __launch_bounds__(256, 2)
gemm_fp16_kernel(const float* __restrict__ bias, float* __restrict__ C) {
    extern __shared__ char smem[];
    uint32_t sbase;
    asm("{ .reg .u64 t; cvta.to.shared.u64 t, %1; cvt.u32.u64 %0, t; }"
        : "=r"(sbase) : "l"(smem));

    const int tid  = threadIdx.x;
    const int lane = tid & 31;
    const int warp = tid >> 5;
    const int wm   = warp & 1;      // 2 warps along M (64 rows each)
    const int wn   = warp >> 1;     // 4 warps along N (32 cols each)
    const int gID  = lane >> 2;
    const int t4   = lane & 3;

    // CTA swizzle: stripes of 16 M-tiles keep B panels L2-resident.
    const int tiles_n = N_TOTAL / 128;   // 86
    const int GRP = 16;
    int gid = blockIdx.x;
    int stripe = gid / (GRP * tiles_n);
    int rem = gid - stripe * (GRP * tiles_n);
    int tm = stripe * GRP + (rem % GRP);
    int tn = rem / GRP;
    const int m0 = tm * 128;
    const int n0 = tn * 128;

    const __half* Ag = g_x + (size_t)m0 * K_TOTAL;
    const __half* Bg = g_W + (size_t)n0 * K_TOTAL;

    float acc[4][4][4];
#pragma unroll
    for (int i = 0; i < 4; i++)
#pragma unroll
        for (int j = 0; j < 4; j++)
#pragma unroll
            for (int k = 0; k < 4; k++) acc[i][j][k] = 0.f;

    // Per-thread cp.async addressing constants
    const int crow = tid >> 3;           // 0..31
    const int ccc  = tid & 7;            // chunk
    const uint32_t cdst_off = (uint32_t)crow * 128 + (uint32_t)((ccc ^ (crow & 7)) << 4);

    auto issueA = [&](int kt, int stage) {
        int kbase = kt * BK;
        uint32_t stg = sbase + stage * STAGE_BYTES;
#pragma unroll
        for (int t = 0; t < 4; t++) {            // A: 128 rows x 8 chunks
            uint32_t dst = stg + t * 4096 + cdst_off;
            const __half* src = Ag + (size_t)(t * 32 + crow) * K_TOTAL + kbase + ccc * 8;
            CP_ASYNC16(dst, src);
        }
    };
    auto issueB = [&](int kt, int stage) {
        int kbase = kt * BK;
        uint32_t stg = sbase + stage * STAGE_BYTES + 16384;
#pragma unroll
        for (int t = 0; t < 4; t++) {            // B: 128 rows x 8 chunks
            uint32_t dst = stg + t * 4096 + cdst_off;
            const __half* src = Bg + (size_t)(t * 32 + crow) * K_TOTAL + kbase + ccc * 8;
            CP_ASYNC16(dst, src);
        }
    };

    // ldmatrix per-thread row/chunk decomposition
    const int arow = (lane & 7) + ((lane >> 3) & 1) * 8;   // 0..15
    const int akp  = lane >> 4;                            // 0/1 (k half)
    const int brow = (lane & 7) + (lane >> 4) * 8;         // 0..15
    const int bkp  = (lane >> 3) & 1;                      // 0/1 (k half)
    const int l7   = lane & 7;

    const uint32_t a_row_off = (uint32_t)(wm * 64 + arow) * 128;
    const uint32_t b_row_off = 16384u + (uint32_t)(wn * 32 + brow) * 128;

    const int NK = K_TOTAL / BK;   // 64

    issueA(0, 0); issueB(0, 0); CP_COMMIT();
    issueA(1, 1); issueB(1, 1); CP_COMMIT();

    int stage = 0;
    for (int kt = 0; kt < NK; kt++) {
        CP_WAIT(1);
        __syncthreads();
        int s2 = stage + 2; if (s2 >= NSTAGE) s2 -= NSTAGE;
        const bool pf = (kt + 2 < NK);
        uint32_t stg = sbase + stage * STAGE_BYTES;

#pragma unroll
        for (int ks = 0; ks < 4; ks++) {
            uint32_t a[4][4], b[2][4];
#pragma unroll
            for (int mt = 0; mt < 4; mt++) {
                uint32_t addr = stg + a_row_off + (uint32_t)(mt * 16) * 128 +
                                (uint32_t)(((2 * ks + akp) ^ l7) << 4);
                LDSM_X4(a[mt][0], a[mt][1], a[mt][2], a[mt][3], addr);
            }
#pragma unroll
            for (int p = 0; p < 2; p++) {
                uint32_t addr = stg + b_row_off + (uint32_t)(p * 16) * 128 +
                                (uint32_t)(((2 * ks + bkp) ^ l7) << 4);
                LDSM_X4(b[p][0], b[p][1], b[p][2], b[p][3], addr);
            }
#pragma unroll
            for (int mt = 0; mt < 4; mt++)
#pragma unroll
                for (int nt = 0; nt < 4; nt++) {
                    uint32_t b0 = b[nt >> 1][(nt & 1) * 2];
                    uint32_t b1 = b[nt >> 1][(nt & 1) * 2 + 1];
                    asm volatile(
                        "mma.sync.aligned.m16n8k16.row.col.f32.f16.f16.f32 "
                        "{%0,%1,%2,%3}, {%4,%5,%6,%7}, {%8,%9}, {%0,%1,%2,%3};\n"
                        : "+f"(acc[mt][nt][0]), "+f"(acc[mt][nt][1]),
                          "+f"(acc[mt][nt][2]), "+f"(acc[mt][nt][3])
                        : "r"(a[mt][0]), "r"(a[mt][1]), "r"(a[mt][2]), "r"(a[mt][3]),
                          "r"(b0), "r"(b1));
                }
            // Interleave next-stage prefetch into the MMA stream: A after
            // ks=0, B + commit after ks=1 (commit every iter keeps the
            // wait_group count uniform; tail iters commit empty groups).
            if (ks == 0 && pf) issueA(kt + 2, s2);
            if (ks == 1) { if (pf) issueB(kt + 2, s2); CP_COMMIT(); }
        }
        stage = (stage + 1 == NSTAGE) ? 0 : stage + 1;
    }

    // Epilogue: bias add + fp32 stores
    float2 bv[4];
#pragma unroll
    for (int nt = 0; nt < 4; nt++) {
        int col = n0 + wn * 32 + nt * 8 + t4 * 2;
        bv[nt] = *reinterpret_cast<const float2*>(bias + col);
    }
#pragma unroll
    for (int mt = 0; mt < 4; mt++) {
#pragma unroll
        for (int nt = 0; nt < 4; nt++) {
            int row0 = m0 + wm * 64 + mt * 16 + gID;
            int col  = n0 + wn * 32 + nt * 8 + t4 * 2;
            float2 v0 = make_float2(acc[mt][nt][0] + bv[nt].x, acc[mt][nt][1] + bv[nt].y);
            float2 v1 = make_float2(acc[mt][nt][2] + bv[nt].x, acc[mt][nt][3] + bv[nt].y);
            *reinterpret_cast<float2*>(C + (size_t)row0 * N_TOTAL + col)       = v0;
            *reinterpret_cast<float2*>(C + (size_t)(row0 + 8) * N_TOTAL + col) = v1;
        }
    }
}

// ---------------------------------------------------------------------------
// Launch. Inputs: x, W_q, scale, zero, bias. Output fp32.
// ---------------------------------------------------------------------------
extern "C" void kernel_launch(void* const* d_in, const int* in_sizes, int n_in,
                              void* d_out, int out_size) {
    const float* x     = (const float*)d_in[0];
    const int*   Wq    = (const int*)d_in[1];
    const float* scale = (const float*)d_in[2];
    const float* zero  = (const float*)d_in[3];
    const float* bias  = (const float*)d_in[4];
    float* out = (float*)d_out;

    {
        int quads = (32 * NGROUPS) / 4;
        int threads = 256;
        int blocks = (quads + threads - 1) / threads;
        dequant_w_kernel<<<blocks, threads>>>((const int4*)Wq,
                                              (const float4*)scale,
                                              (const float4*)zero);
    }
    {
        int n8 = (M_TOTAL * K_TOTAL) / 8;
        int threads = 256;
        int blocks = (n8 + threads - 1) / threads;
        convx_kernel<<<blocks, threads>>>((const float4*)x, n8);
    }
    {
        cudaFuncSetAttribute(gemm_fp16_kernel,
                             cudaFuncAttributeMaxDynamicSharedMemorySize, SMEM_TOTAL);
        int blocks = (M_TOTAL / 128) * (N_TOTAL / 128);   // 5504
        gemm_fp16_kernel<<<blocks, 256, SMEM_TOTAL>>>(bias, out);
    }
}